// round 3
// baseline (speedup 1.0000x reference)
#include <cuda_runtime.h>

// out[b,o] = sum_{i<64, l<32} obs[b,i,l,o] * ctx[b, 31-l, i]
// obs[b] flattened over (i,l,o): offset = p*64 + o, p = i*32 + l (contiguous).
// One CTA per TWO batch elements -> grid=1024 (single wave on 148 SMs @ occ 8).
// 256 threads = 16 groups x 16 lanes; lane owns 4 o-values (float4).
// Two independent accumulator streams (b0, b1) per thread for 2x MLP.

#define B_DIM 2048
#define R_DIM 32
#define O_DIM 64
#define PAIRS 2048           // 64*32
#define GROUPS 16
#define PAIRS_PER_GROUP (PAIRS / GROUPS)   // 128

__global__ __launch_bounds__(256, 8)
void cnnkf_kernel(const float* __restrict__ ctx,
                  const float* __restrict__ obs,
                  float* __restrict__ out) {
    __shared__ float s_ctx[2][R_DIM * O_DIM];     // 16 KB: ctx for b0, b1
    __shared__ float s_part[2][GROUPS][O_DIM];    // 8 KB: per-group partials

    const int b0  = blockIdx.x * 2;
    const int tid = threadIdx.x;

    // Stage both context slices (2 x 2048 floats), coalesced.
    const float* __restrict__ ctx_b = ctx + (size_t)b0 * (R_DIM * O_DIM);
    #pragma unroll
    for (int k = 0; k < (2 * R_DIM * O_DIM) / 256; k++) {
        (&s_ctx[0][0])[k * 256 + tid] = ctx_b[k * 256 + tid];
    }
    __syncthreads();

    const int group = tid >> 4;   // 0..15
    const int olane = tid & 15;   // 0..15  -> o = olane*4 .. +3

    float4 acc0 = make_float4(0.f, 0.f, 0.f, 0.f);
    float4 acc1 = make_float4(0.f, 0.f, 0.f, 0.f);

    const float4* __restrict__ base0 =
        reinterpret_cast<const float4*>(obs + (size_t)b0 * (size_t)(PAIRS * O_DIM));
    const float4* __restrict__ base1 = base0 + PAIRS * 16;

    #pragma unroll 4
    for (int j = 0; j < PAIRS_PER_GROUP; j++) {
        const int p   = j * GROUPS + group;      // warp -> contiguous 512B per stream
        const int idx = p * 16 + olane;
        const float4 v0 = __ldcs(&base0[idx]);   // evict-first: single-use stream
        const float4 v1 = __ldcs(&base1[idx]);
        const int l = p & 31;
        const int i = p >> 5;
        const int coff = (31 - l) * O_DIM + i;
        const float c0 = s_ctx[0][coff];
        const float c1 = s_ctx[1][coff];
        acc0.x = fmaf(c0, v0.x, acc0.x);
        acc0.y = fmaf(c0, v0.y, acc0.y);
        acc0.z = fmaf(c0, v0.z, acc0.z);
        acc0.w = fmaf(c0, v0.w, acc0.w);
        acc1.x = fmaf(c1, v1.x, acc1.x);
        acc1.y = fmaf(c1, v1.y, acc1.y);
        acc1.z = fmaf(c1, v1.z, acc1.z);
        acc1.w = fmaf(c1, v1.w, acc1.w);
    }

    *reinterpret_cast<float4*>(&s_part[0][group][olane * 4]) = acc0;
    *reinterpret_cast<float4*>(&s_part[1][group][olane * 4]) = acc1;
    __syncthreads();

    // Cross-group reduction: 128 threads -> (which_b, o)
    if (tid < 2 * O_DIM) {
        const int wb = tid >> 6;       // 0 or 1
        const int o  = tid & 63;
        float s = 0.f;
        #pragma unroll
        for (int g = 0; g < GROUPS; g++) s += s_part[wb][g][o];
        out[(size_t)(b0 + wb) * O_DIM + o] = s;
    }
}

extern "C" void kernel_launch(void* const* d_in, const int* in_sizes, int n_in,
                              void* d_out, int out_size) {
    const float* ctx = (const float*)d_in[0];   // context      (B, R, O)
    const float* obs = (const float*)d_in[1];   // observation  (B, O, R, O)
    float* out = (float*)d_out;                  // (B, O)

    cnnkf_kernel<<<B_DIM / 2, 256>>>(ctx, obs, out);
}

// round 4
// speedup vs baseline: 1.2465x; 1.2465x over previous
#include <cuda_runtime.h>

// out[b,o] = sum_{i<64, l<32} obs[b,i,l,o] * ctx[b, 31-l, i]
// obs[b] flattened over (i,l,o): offset = p*64 + o, p = i*32 + l (contiguous).
// One CTA per b, 128 threads -> up to 16 CTAs/SM resident: grid 2048 fits in
// ONE wave (148*16 = 2368 slots), no tail, full 2048-thread/SM occupancy.
// 128 threads = 8 groups x 16 lanes; lane owns 4 o-values (float4).
// Warp = 2 adjacent groups -> each step issues one contiguous 512B transaction.

#define B_DIM 2048
#define R_DIM 32
#define O_DIM 64
#define PAIRS 2048           // 64*32
#define GROUPS 8
#define PAIRS_PER_GROUP (PAIRS / GROUPS)   // 256

__global__ __launch_bounds__(128, 16)
void cnnkf_kernel(const float* __restrict__ ctx,
                  const float* __restrict__ obs,
                  float* __restrict__ out) {
    __shared__ float s_ctx[R_DIM * O_DIM];       // 8 KB: ctx[b] row-major [r][i]
    __shared__ float s_part[GROUPS][O_DIM];      // 2 KB: per-group partial sums

    const int b   = blockIdx.x;
    const int tid = threadIdx.x;

    const float* __restrict__ ctx_b = ctx + (size_t)b * (R_DIM * O_DIM);
    const float* __restrict__ obs_b = obs + (size_t)b * (size_t)(PAIRS * O_DIM);

    // Stage context slice (2048 floats) into smem, coalesced.
    #pragma unroll
    for (int k = 0; k < (R_DIM * O_DIM) / 128; k++) {
        s_ctx[k * 128 + tid] = ctx_b[k * 128 + tid];
    }
    __syncthreads();

    const int group = tid >> 4;   // 0..7
    const int olane = tid & 15;   // 0..15  -> o = olane*4 .. olane*4+3

    float4 acc = make_float4(0.f, 0.f, 0.f, 0.f);

    // float4 view: element (p, o4) at index p*16 + o4
    const float4* __restrict__ base = reinterpret_cast<const float4*>(obs_b);

    #pragma unroll 8
    for (int j = 0; j < PAIRS_PER_GROUP; j++) {
        const int p = j * GROUPS + group;        // warp (2 groups) -> contiguous 512B
        const float4 v = base[p * 16 + olane];
        const int l = p & 31;
        const int i = p >> 5;
        const float c = s_ctx[(31 - l) * O_DIM + i];   // broadcast within group
        acc.x = fmaf(c, v.x, acc.x);
        acc.y = fmaf(c, v.y, acc.y);
        acc.z = fmaf(c, v.z, acc.z);
        acc.w = fmaf(c, v.w, acc.w);
    }

    // Write partials
    *reinterpret_cast<float4*>(&s_part[group][olane * 4]) = acc;
    __syncthreads();

    // Cross-group reduction: 64 threads, one per o
    if (tid < O_DIM) {
        float s = 0.f;
        #pragma unroll
        for (int g = 0; g < GROUPS; g++) s += s_part[g][tid];
        out[(size_t)b * O_DIM + tid] = s;
    }
}

extern "C" void kernel_launch(void* const* d_in, const int* in_sizes, int n_in,
                              void* d_out, int out_size) {
    const float* ctx = (const float*)d_in[0];   // context      (B, R, O)
    const float* obs = (const float*)d_in[1];   // observation  (B, O, R, O)
    float* out = (float*)d_out;                  // (B, O)

    cnnkf_kernel<<<B_DIM, 128>>>(ctx, obs, out);
}